// round 12
// baseline (speedup 1.0000x reference)
#include <cuda_runtime.h>
#include <stdint.h>

#define EPS 1e-10f
#define BLOCK 256
#define MAX_B 4096

// Per-row winners, packed u64: high 32 = order-preserving key bits,
// low 32 = ~idx (equal key -> LOWER index wins max; jnp.argmax tie rule).
// Zero at module load; self-cleaned by the last CTA each launch.
__device__ unsigned long long g_best[MAX_B];
__device__ int g_done;

__device__ __forceinline__ unsigned int order_f32(float f)
{
    unsigned int u = __float_as_uint(f);
    unsigned int m = ((int)u >> 31) | 0x80000000u;
    return u ^ m;  // monotone float -> uint
}

// Flat byte-balanced kernel.
// Work units: greedy row (t==0) = V units (reads logits only),
//             sampled row        = 2V units (reads logits + noise).
// Each CTA takes an equal slice of [0, U); slice boundaries rounded to 8
// units so per-row element ranges stay float4-aligned for both weights.
// Key math: argmax( softmax(l/t)/(n+EPS) ) == argmax( l/t - log(n+EPS) ).
__global__ __launch_bounds__(BLOCK, 4) void draft_sampler_kernel(
    const float* __restrict__ big0,
    const float* __restrict__ big1,
    const float* __restrict__ temps,
    float* __restrict__ out,
    int B, int V)
{
    const int tid = threadIdx.x;
    const int G = gridDim.x;

    // ---- Prefix sum of per-row unit weights (B <= BLOCK assumed; B=256) ----
    __shared__ unsigned sC[BLOCK + 1];
    __shared__ unsigned sWarp[BLOCK / 32];

    unsigned w = 0;
    if (tid < B) w = (temps[tid] == 0.0f) ? (unsigned)V : (unsigned)(2 * V);
    unsigned v = w;
    #pragma unroll
    for (int off = 1; off < 32; off <<= 1) {
        unsigned u = __shfl_up_sync(0xFFFFFFFFu, v, off);
        if ((tid & 31) >= off) v += u;
    }
    if ((tid & 31) == 31) sWarp[tid >> 5] = v;
    __syncthreads();
    if (tid < BLOCK / 32) {
        unsigned x = sWarp[tid];
        #pragma unroll
        for (int off = 1; off < BLOCK / 32; off <<= 1) {
            unsigned u = __shfl_up_sync(0xFFu, x, off);
            if (tid >= off) x += u;
        }
        sWarp[tid] = x;
    }
    __syncthreads();
    const unsigned warpOff = (tid >= 32) ? sWarp[(tid >> 5) - 1] : 0u;
    if (tid < B) sC[tid + 1] = v + warpOff;
    if (tid == 0) sC[0] = 0u;
    __syncthreads();

    const unsigned U = sC[B];  // total units (~496*V < 2^31)

    const unsigned long long Ul = (unsigned long long)U;
    const unsigned myStart = (unsigned)((Ul * blockIdx.x / G) & ~7ull);
    const unsigned myEnd = (blockIdx.x == G - 1)
                               ? U
                               : (unsigned)((Ul * (blockIdx.x + 1) / G) & ~7ull);

    // ---- Locate starting row ----
    __shared__ int s_startRow;
    if (tid < B && sC[tid] <= myStart && myStart < sC[tid + 1]) s_startRow = tid;
    __syncthreads();
    const int startRow = s_startRow;

    // ---- Per-CTA detection: big0 == logits (has negatives)? P(err)=2^-128 ----
    __shared__ int s_is_logits;
    if (tid < 32) {
        const unsigned c0 = sC[startRow], c1 = sC[startRow + 1];
        const int wr = ((c1 - c0) == (unsigned)V) ? 1 : 2;
        long long off = (long long)startRow * V + (long long)((myStart - c0) / wr);
        const long long lim = (long long)B * V - 128;
        if (off > lim) off = lim;
        bool neg = false;
        #pragma unroll
        for (int k = 0; k < 4; k++) neg |= (big0[off + tid + 32 * k] < 0.0f);
        unsigned m = __ballot_sync(0xFFFFFFFFu, neg);
        if (tid == 0) s_is_logits = (m != 0u);
    }
    __syncthreads();

    const float* __restrict__ logits = s_is_logits ? big0 : big1;
    const float* __restrict__ noise  = s_is_logits ? big1 : big0;

    __shared__ unsigned long long sbest[BLOCK / 32];

#define TAKE(K, IDX) if ((K) > bestKey) { bestKey = (K); bestIdx = (IDX); }
#define SCAN_L(V4, BI)      \
    TAKE((V4).x, (BI));     \
    TAKE((V4).y, (BI) + 1); \
    TAKE((V4).z, (BI) + 2); \
    TAKE((V4).w, (BI) + 3)
#define SCAN_K(LV, NV, BI)                                    \
    TAKE((LV).x * inv_t - __logf((NV).x + EPS), (BI));        \
    TAKE((LV).y * inv_t - __logf((NV).y + EPS), (BI) + 1);    \
    TAKE((LV).z * inv_t - __logf((NV).z + EPS), (BI) + 2);    \
    TAKE((LV).w * inv_t - __logf((NV).w + EPS), (BI) + 3)

    // ---- Process rows overlapping [myStart, myEnd) ----
    for (int r = startRow; r < B; r++) {
        const unsigned c0 = sC[r], c1 = sC[r + 1];
        if (c0 >= myEnd) break;
        const unsigned su = (myStart > c0) ? myStart : c0;
        const unsigned eu = (myEnd < c1) ? myEnd : c1;
        if (su >= eu) continue;

        const bool greedy = ((c1 - c0) == (unsigned)V);
        const int wr = greedy ? 1 : 2;
        const int i0 = (int)((su - c0) / wr) >> 2;  // float4 index range
        const int i1 = (int)((eu - c0) / wr) >> 2;

        const float t = temps[r];
        const float inv_t = greedy ? 1.0f : (1.0f / t);
        const long long rowBase = (long long)r * V;
        const float4* __restrict__ l4 =
            reinterpret_cast<const float4*>(logits + rowBase);
        const float4* __restrict__ n4 =
            reinterpret_cast<const float4*>(noise + rowBase);

        float bestKey = -3.402823466e38f;
        int   bestIdx = 0;

        int i = i0 + tid;
        if (greedy) {
            for (; i + 3 * BLOCK < i1; i += 4 * BLOCK) {
                const float4 a0 = __ldcs(&l4[i]);
                const float4 a1 = __ldcs(&l4[i + BLOCK]);
                const float4 a2 = __ldcs(&l4[i + 2 * BLOCK]);
                const float4 a3 = __ldcs(&l4[i + 3 * BLOCK]);
                SCAN_L(a0, i << 2);
                SCAN_L(a1, (i + BLOCK) << 2);
                SCAN_L(a2, (i + 2 * BLOCK) << 2);
                SCAN_L(a3, (i + 3 * BLOCK) << 2);
            }
            for (; i < i1; i += BLOCK) {
                const float4 a = __ldcs(&l4[i]);
                SCAN_L(a, i << 2);
            }
        } else {
            for (; i + 3 * BLOCK < i1; i += 4 * BLOCK) {
                const float4 a0 = __ldcs(&l4[i]);
                const float4 a1 = __ldcs(&l4[i + BLOCK]);
                const float4 a2 = __ldcs(&l4[i + 2 * BLOCK]);
                const float4 a3 = __ldcs(&l4[i + 3 * BLOCK]);
                const float4 b0 = __ldcs(&n4[i]);
                const float4 b1 = __ldcs(&n4[i + BLOCK]);
                const float4 b2 = __ldcs(&n4[i + 2 * BLOCK]);
                const float4 b3 = __ldcs(&n4[i + 3 * BLOCK]);
                SCAN_K(a0, b0, i << 2);
                SCAN_K(a1, b1, (i + BLOCK) << 2);
                SCAN_K(a2, b2, (i + 2 * BLOCK) << 2);
                SCAN_K(a3, b3, (i + 3 * BLOCK) << 2);
            }
            for (; i < i1; i += BLOCK) {
                const float4 a = __ldcs(&l4[i]);
                const float4 b = __ldcs(&n4[i]);
                SCAN_K(a, b, i << 2);
            }
        }

        // Block reduction on packed u64 (tie-break folded into ~idx).
        unsigned long long best =
            ((unsigned long long)order_f32(bestKey) << 32) |
            (unsigned int)(~bestIdx);
        #pragma unroll
        for (int off = 16; off > 0; off >>= 1) {
            unsigned long long o = __shfl_down_sync(0xFFFFFFFFu, best, off);
            if (o > best) best = o;
        }
        if ((tid & 31) == 0) sbest[tid >> 5] = best;
        __syncthreads();
        if (tid == 0) {
            #pragma unroll
            for (int q = 1; q < BLOCK / 32; q++)
                if (sbest[q] > best) best = sbest[q];
            atomicMax(&g_best[r], best);
        }
        __syncthreads();
    }

    // ---- Last CTA writes outputs and self-cleans scratch ----
    __threadfence();
    __shared__ int s_last;
    if (tid == 0) s_last = (atomicAdd(&g_done, 1) == G - 1);
    __syncthreads();
    if (s_last) {
        __threadfence();
        for (int r = tid; r < B; r += BLOCK) {
            const unsigned long long m = g_best[r];
            out[r] = (float)(~(unsigned int)(m & 0xFFFFFFFFull));  // id < 2^24: exact
            g_best[r] = 0ull;
        }
        if (tid == 0) g_done = 0;
    }
}

extern "C" void kernel_launch(void* const* d_in, const int* in_sizes, int n_in,
                              void* d_out, int out_size)
{
    // Identify inputs by SIZE, not order: temperatures -> unique smallest [B];
    // logits/exp_noise -> the big pair (disambiguated on-device by sign).
    int smallIdx = 0;
    for (int i = 1; i < n_in; i++)
        if (in_sizes[i] < in_sizes[smallIdx]) smallIdx = i;

    int bigIdx0 = -1, bigIdx1 = -1;
    for (int i = 0; i < n_in; i++) {
        if (i == smallIdx) continue;
        if (bigIdx0 < 0) bigIdx0 = i; else bigIdx1 = i;
    }

    const float* temps = (const float*)d_in[smallIdx];
    const float* big0  = (const float*)d_in[bigIdx0];
    const float* big1  = (const float*)d_in[bigIdx1];
    float* out = (float*)d_out;                 // __output__ is float32

    const int B = in_sizes[smallIdx];           // 256
    const int V = in_sizes[bigIdx0] / B;        // 128000

    int nsm = 148;
    cudaDeviceGetAttribute(&nsm, cudaDevAttrMultiProcessorCount, 0);
    const int G = 4 * nsm;                      // one exact wave at 4 CTAs/SM

    draft_sampler_kernel<<<G, BLOCK>>>(big0, big1, temps, out, B, V);
}

// round 13
// speedup vs baseline: 1.0177x; 1.0177x over previous
#include <cuda_runtime.h>
#include <stdint.h>

#define EPS 1e-10f
#define BLOCK 256
#define MAX_B 4096

// Per-row winners, packed u64: high 32 = order-preserving key bits,
// low 32 = ~idx (equal key -> LOWER index wins max; jnp.argmax tie rule).
// Zeroed at module load; self-cleaned by the last CTA each launch.
__device__ unsigned long long g_best[MAX_B];
__device__ unsigned int g_work;  // chunk pop counter (reset each launch)
__device__ int g_done;           // completion counter (reset each launch)

__device__ __forceinline__ unsigned int order_f32(float f)
{
    unsigned int u = __float_as_uint(f);
    unsigned int m = ((int)u >> 31) | 0x80000000u;
    return u ^ m;  // monotone float -> uint
}

// Persistent work-stealing kernel over UNIFORM-BYTE chunks:
//   sampled row (t>0): 8 chunks, each V/8 elems of logits+noise (128 KB)
//   greedy  row (t==0): 4 chunks, each V/4 elems of logits only (128 KB)
// Key math: argmax( softmax(l/t)/(n+EPS) ) == argmax( l/t - log(n+EPS) ).
__global__ __launch_bounds__(BLOCK, 4) void draft_sampler_kernel(
    const float* __restrict__ big0,
    const float* __restrict__ big1,
    const float* __restrict__ temps,
    float* __restrict__ out,
    int B, int V)
{
    const int tid = threadIdx.x;
    const int G = gridDim.x;

    // ---- Prefix sum of per-row CHUNK counts (B <= BLOCK; B=256) ----
    __shared__ unsigned sC[BLOCK + 1];
    __shared__ unsigned sWarp[BLOCK / 32];

    unsigned w = 0;
    if (tid < B) w = (temps[tid] == 0.0f) ? 4u : 8u;
    unsigned v = w;
    #pragma unroll
    for (int off = 1; off < 32; off <<= 1) {
        unsigned u = __shfl_up_sync(0xFFFFFFFFu, v, off);
        if ((tid & 31) >= off) v += u;
    }
    if ((tid & 31) == 31) sWarp[tid >> 5] = v;
    __syncthreads();
    if (tid < BLOCK / 32) {
        unsigned x = sWarp[tid];
        #pragma unroll
        for (int off = 1; off < BLOCK / 32; off <<= 1) {
            unsigned u = __shfl_up_sync(0xFFu, x, off);
            if (tid >= off) x += u;
        }
        sWarp[tid] = x;
    }
    __syncthreads();
    const unsigned warpOff = (tid >= 32) ? sWarp[(tid >> 5) - 1] : 0u;
    if (tid < B) sC[tid + 1] = v + warpOff;
    if (tid == 0) sC[0] = 0u;
    __syncthreads();
    const unsigned NC = sC[B];  // total chunks (1984 for B=256)

    // ---- Detection: big0 == logits (has negatives)? P(err) = 2^-128.
    // Fixed 512B region -> L2-resident after the first CTA touches it.
    __shared__ int s_is_logits;
    if (tid < 32) {
        bool neg = false;
        #pragma unroll
        for (int k = 0; k < 4; k++) neg |= (big0[tid + 32 * k] < 0.0f);
        unsigned m = __ballot_sync(0xFFFFFFFFu, neg);
        if (tid == 0) s_is_logits = (m != 0u);
    }

    __shared__ unsigned s_next;
    __shared__ unsigned long long sbest[BLOCK / 32];
    if (tid == 0) s_next = atomicAdd(&g_work, 1u);
    __syncthreads();

    const float* __restrict__ logits = s_is_logits ? big0 : big1;
    const float* __restrict__ noise  = s_is_logits ? big1 : big0;

#define TAKE(K, IDX) if ((K) > bestKey) { bestKey = (K); bestIdx = (IDX); }
#define SCAN_L(V4, BI)      \
    TAKE((V4).x, (BI));     \
    TAKE((V4).y, (BI) + 1); \
    TAKE((V4).z, (BI) + 2); \
    TAKE((V4).w, (BI) + 3)
#define SCAN_K(LV, NV, BI)                                    \
    TAKE((LV).x * inv_t - __logf((NV).x + EPS), (BI));        \
    TAKE((LV).y * inv_t - __logf((NV).y + EPS), (BI) + 1);    \
    TAKE((LV).z * inv_t - __logf((NV).z + EPS), (BI) + 2);    \
    TAKE((LV).w * inv_t - __logf((NV).w + EPS), (BI) + 3)

    for (;;) {
        const unsigned c = s_next;     // uniform across block
        __syncthreads();               // everyone read c before overwrite
        if (c >= NC) break;
        if (tid == 0) s_next = atomicAdd(&g_work, 1u);  // prefetch next id

        // ---- chunk id -> row (binary search on smem prefix; uniform) ----
        int lo = 0, hi = B;
        while (hi - lo > 1) {
            const int mid = (lo + hi) >> 1;
            if (sC[mid] <= c) lo = mid; else hi = mid;
        }
        const int r = lo;
        const unsigned segIdx = c - sC[r];
        const float t = temps[r];
        const bool greedy = (t == 0.0f);
        const float inv_t = greedy ? 1.0f : (1.0f / t);
        const int nSeg = greedy ? 4 : 8;
        const int chunkF4 = greedy ? (V >> 4) : (V >> 5);
        const int i0 = (int)segIdx * chunkF4;
        const int i1 = ((int)segIdx == nSeg - 1) ? (V >> 2) : i0 + chunkF4;

        const long long rowBase = (long long)r * V;
        const float4* __restrict__ l4 =
            reinterpret_cast<const float4*>(logits + rowBase);
        const float4* __restrict__ n4 =
            reinterpret_cast<const float4*>(noise + rowBase);

        float bestKey = -3.402823466e38f;
        int   bestIdx = 0;

        int i = i0 + tid;
        if (greedy) {
            for (; i + 3 * BLOCK < i1; i += 4 * BLOCK) {
                const float4 a0 = __ldcs(&l4[i]);
                const float4 a1 = __ldcs(&l4[i + BLOCK]);
                const float4 a2 = __ldcs(&l4[i + 2 * BLOCK]);
                const float4 a3 = __ldcs(&l4[i + 3 * BLOCK]);
                SCAN_L(a0, i << 2);
                SCAN_L(a1, (i + BLOCK) << 2);
                SCAN_L(a2, (i + 2 * BLOCK) << 2);
                SCAN_L(a3, (i + 3 * BLOCK) << 2);
            }
            for (; i < i1; i += BLOCK) {
                const float4 a = __ldcs(&l4[i]);
                SCAN_L(a, i << 2);
            }
        } else {
            for (; i + 3 * BLOCK < i1; i += 4 * BLOCK) {
                const float4 a0 = __ldcs(&l4[i]);
                const float4 a1 = __ldcs(&l4[i + BLOCK]);
                const float4 a2 = __ldcs(&l4[i + 2 * BLOCK]);
                const float4 a3 = __ldcs(&l4[i + 3 * BLOCK]);
                const float4 b0 = __ldcs(&n4[i]);
                const float4 b1 = __ldcs(&n4[i + BLOCK]);
                const float4 b2 = __ldcs(&n4[i + 2 * BLOCK]);
                const float4 b3 = __ldcs(&n4[i + 3 * BLOCK]);
                SCAN_K(a0, b0, i << 2);
                SCAN_K(a1, b1, (i + BLOCK) << 2);
                SCAN_K(a2, b2, (i + 2 * BLOCK) << 2);
                SCAN_K(a3, b3, (i + 3 * BLOCK) << 2);
            }
            for (; i < i1; i += BLOCK) {
                const float4 a = __ldcs(&l4[i]);
                const float4 b = __ldcs(&n4[i]);
                SCAN_K(a, b, i << 2);
            }
        }

        // ---- Block reduction on packed u64 (tie-break folded into ~idx) ----
        unsigned long long best =
            ((unsigned long long)order_f32(bestKey) << 32) |
            (unsigned int)(~bestIdx);
        #pragma unroll
        for (int off = 16; off > 0; off >>= 1) {
            unsigned long long o = __shfl_down_sync(0xFFFFFFFFu, best, off);
            if (o > best) best = o;
        }
        if ((tid & 31) == 0) sbest[tid >> 5] = best;
        __syncthreads();
        if (tid == 0) {
            #pragma unroll
            for (int q = 1; q < BLOCK / 32; q++)
                if (sbest[q] > best) best = sbest[q];
            atomicMax(&g_best[r], best);
        }
        __syncthreads();  // protects sbest reuse + makes s_next visible
    }

    // ---- Last CTA writes outputs and self-cleans all scratch ----
    __threadfence();
    __shared__ int s_last;
    if (tid == 0) s_last = (atomicAdd(&g_done, 1) == G - 1);
    __syncthreads();
    if (s_last) {
        __threadfence();
        for (int r = tid; r < B; r += BLOCK) {
            const unsigned long long m = g_best[r];
            out[r] = (float)(~(unsigned int)(m & 0xFFFFFFFFull));  // id < 2^24: exact
            g_best[r] = 0ull;
        }
        if (tid == 0) { g_work = 0u; g_done = 0; }
    }
}

extern "C" void kernel_launch(void* const* d_in, const int* in_sizes, int n_in,
                              void* d_out, int out_size)
{
    // Identify inputs by SIZE, not order: temperatures -> unique smallest [B];
    // logits/exp_noise -> the big pair (disambiguated on-device by sign).
    int smallIdx = 0;
    for (int i = 1; i < n_in; i++)
        if (in_sizes[i] < in_sizes[smallIdx]) smallIdx = i;

    int bigIdx0 = -1, bigIdx1 = -1;
    for (int i = 0; i < n_in; i++) {
        if (i == smallIdx) continue;
        if (bigIdx0 < 0) bigIdx0 = i; else bigIdx1 = i;
    }

    const float* temps = (const float*)d_in[smallIdx];
    const float* big0  = (const float*)d_in[bigIdx0];
    const float* big1  = (const float*)d_in[bigIdx1];
    float* out = (float*)d_out;                 // __output__ is float32

    const int B = in_sizes[smallIdx];           // 256
    const int V = in_sizes[bigIdx0] / B;        // 128000

    int nsm = 148;
    cudaDeviceGetAttribute(&nsm, cudaDevAttrMultiProcessorCount, 0);
    const int G = 4 * nsm;                      // persistent: one exact wave

    draft_sampler_kernel<<<G, BLOCK>>>(big0, big1, temps, out, B, V);
}

// round 14
// speedup vs baseline: 1.1428x; 1.1229x over previous
#include <cuda_runtime.h>
#include <stdint.h>

#define EPS 1e-10f
#define BLOCK 256
#define MAX_B 4096

// Per-(row,slot) winners, packed u64: high 32 = order-preserving key bits,
// low 32 = ~idx (equal key -> LOWER index wins max; jnp.argmax tie rule).
__device__ unsigned long long g_seg[MAX_B * 2];
// Per-row arrival counters; zero at module load, reset by each row's
// finalizer every launch -> clean across graph replays.
__device__ int g_count[MAX_B];

__device__ __forceinline__ unsigned int order_f32(float f)
{
    unsigned int u = __float_as_uint(f);
    unsigned int m = ((int)u >> 31) | 0x80000000u;
    return u ^ m;  // monotone float -> uint
}

// Byte-uniform chunks, one contiguous stream per CTA, zero mid-stream syncs:
//   sampled row (t>0): 2 chunks of V/2 elems, reads logits+noise  (512 KB)
//   greedy  row (t==0): 1 chunk of V elems, reads logits only     (512 KB)
// Key math: argmax( softmax(l/t)/(n+EPS) ) == argmax( l/t - log(n+EPS) )
// (softmax shift/normalizer are row constants; log is monotone).
__global__ __launch_bounds__(BLOCK, 4) void draft_sampler_kernel(
    const float* __restrict__ big0,
    const float* __restrict__ big1,
    const float* __restrict__ temps,
    float* __restrict__ out,
    int B, int V)
{
    const int tid = threadIdx.x;

    // ---- Prefix sum of per-row chunk counts (B <= BLOCK; B=256) ----
    __shared__ unsigned sC[BLOCK + 1];
    __shared__ unsigned sWarp[BLOCK / 32];

    unsigned w = 0;
    if (tid < B) w = (temps[tid] == 0.0f) ? 1u : 2u;
    unsigned v = w;
    #pragma unroll
    for (int off = 1; off < 32; off <<= 1) {
        unsigned u = __shfl_up_sync(0xFFFFFFFFu, v, off);
        if ((tid & 31) >= off) v += u;
    }
    if ((tid & 31) == 31) sWarp[tid >> 5] = v;
    __syncthreads();
    if (tid < BLOCK / 32) {
        unsigned x = sWarp[tid];
        #pragma unroll
        for (int off = 1; off < BLOCK / 32; off <<= 1) {
            unsigned u = __shfl_up_sync(0xFFu, x, off);
            if (tid >= off) x += u;
        }
        sWarp[tid] = x;
    }
    __syncthreads();
    const unsigned warpOff = (tid >= 32) ? sWarp[(tid >> 5) - 1] : 0u;
    if (tid < B) sC[tid + 1] = v + warpOff;
    if (tid == 0) sC[0] = 0u;
    __syncthreads();
    const unsigned NC = sC[B];           // active chunks (<= 2B)

    const unsigned c = blockIdx.x;
    if (c >= NC) return;                 // surplus CTA: no work this launch

    // ---- chunk id -> (row, seg) via binary search on prefix ----
    int lo = 0, hi = B;
    while (hi - lo > 1) {
        const int mid = (lo + hi) >> 1;
        if (sC[mid] <= c) lo = mid; else hi = mid;
    }
    const int row = lo;
    const int seg = (int)(c - sC[row]);
    const float t = temps[row];
    const bool greedy = (t == 0.0f);
    const float inv_t = greedy ? 1.0f : (1.0f / t);
    const int nSeg = greedy ? 1 : 2;

    const int nvec = V >> 2;             // V % 4 == 0 (128000)
    const int i0 = greedy ? 0 : seg * (nvec >> 1);
    const int i1 = greedy ? nvec : ((seg == 1) ? nvec : (nvec >> 1));

    const long long rowBase = (long long)row * V;

    // ---- Per-CTA detection: big0 == logits (has negatives)? P(err)=2^-128.
    // Samples 128 floats from this CTA's own segment (re-read from cache later).
    __shared__ int s_is_logits;
    if (tid < 32) {
        const float* p = big0 + rowBase + ((long long)i0 << 2);
        bool neg = false;
        #pragma unroll
        for (int k = 0; k < 4; k++) neg |= (p[tid + 32 * k] < 0.0f);
        unsigned m = __ballot_sync(0xFFFFFFFFu, neg);
        if (tid == 0) s_is_logits = (m != 0u);
    }
    __syncthreads();

    const float* __restrict__ logits = s_is_logits ? big0 : big1;
    const float* __restrict__ noise  = s_is_logits ? big1 : big0;

    const float4* __restrict__ l4 =
        reinterpret_cast<const float4*>(logits + rowBase);
    const float4* __restrict__ n4 =
        reinterpret_cast<const float4*>(noise + rowBase);

    float bestKey = -3.402823466e38f;
    int   bestIdx = 0;

#define TAKE(K, IDX) if ((K) > bestKey) { bestKey = (K); bestIdx = (IDX); }
#define SCAN_L(V4, BI)      \
    TAKE((V4).x, (BI));     \
    TAKE((V4).y, (BI) + 1); \
    TAKE((V4).z, (BI) + 2); \
    TAKE((V4).w, (BI) + 3)
#define SCAN_K(LV, NV, BI)                                    \
    TAKE((LV).x * inv_t - __logf((NV).x + EPS), (BI));        \
    TAKE((LV).y * inv_t - __logf((NV).y + EPS), (BI) + 1);    \
    TAKE((LV).z * inv_t - __logf((NV).z + EPS), (BI) + 2);    \
    TAKE((LV).w * inv_t - __logf((NV).w + EPS), (BI) + 3)

    int i = i0 + tid;
    if (greedy) {
        // 4-deep unroll: 4 independent LDG.128 in flight per thread.
        for (; i + 3 * BLOCK < i1; i += 4 * BLOCK) {
            const float4 a0 = __ldcs(&l4[i]);
            const float4 a1 = __ldcs(&l4[i + BLOCK]);
            const float4 a2 = __ldcs(&l4[i + 2 * BLOCK]);
            const float4 a3 = __ldcs(&l4[i + 3 * BLOCK]);
            SCAN_L(a0, i << 2);
            SCAN_L(a1, (i + BLOCK) << 2);
            SCAN_L(a2, (i + 2 * BLOCK) << 2);
            SCAN_L(a3, (i + 3 * BLOCK) << 2);
        }
        for (; i < i1; i += BLOCK) {
            const float4 a = __ldcs(&l4[i]);
            SCAN_L(a, i << 2);
        }
    } else {
        // 4-deep unroll: 8 independent LDG.128 in flight per thread.
        for (; i + 3 * BLOCK < i1; i += 4 * BLOCK) {
            const float4 a0 = __ldcs(&l4[i]);
            const float4 a1 = __ldcs(&l4[i + BLOCK]);
            const float4 a2 = __ldcs(&l4[i + 2 * BLOCK]);
            const float4 a3 = __ldcs(&l4[i + 3 * BLOCK]);
            const float4 b0 = __ldcs(&n4[i]);
            const float4 b1 = __ldcs(&n4[i + BLOCK]);
            const float4 b2 = __ldcs(&n4[i + 2 * BLOCK]);
            const float4 b3 = __ldcs(&n4[i + 3 * BLOCK]);
            SCAN_K(a0, b0, i << 2);
            SCAN_K(a1, b1, (i + BLOCK) << 2);
            SCAN_K(a2, b2, (i + 2 * BLOCK) << 2);
            SCAN_K(a3, b3, (i + 3 * BLOCK) << 2);
        }
        for (; i < i1; i += BLOCK) {
            const float4 a = __ldcs(&l4[i]);
            const float4 b = __ldcs(&n4[i]);
            SCAN_K(a, b, i << 2);
        }
    }

    // ---- Single end-of-stream block reduction on packed u64 ----
    unsigned long long best =
        ((unsigned long long)order_f32(bestKey) << 32) | (unsigned int)(~bestIdx);
    #pragma unroll
    for (int off = 16; off > 0; off >>= 1) {
        unsigned long long o = __shfl_down_sync(0xFFFFFFFFu, best, off);
        if (o > best) best = o;
    }

    __shared__ unsigned long long sbest[BLOCK / 32];
    if ((tid & 31) == 0) sbest[tid >> 5] = best;
    __syncthreads();

    if (tid == 0) {
        #pragma unroll
        for (int q = 1; q < BLOCK / 32; q++)
            if (sbest[q] > best) best = sbest[q];

        // Publish this chunk's result; last-arriving chunk finalizes the row.
        g_seg[row * 2 + seg] = best;
        __threadfence();
        const int old = atomicAdd(&g_count[row], 1);
        if (old == nSeg - 1) {
            unsigned long long m = g_seg[row * 2];
            if (nSeg == 2) {
                const unsigned long long v2 = g_seg[row * 2 + 1];
                if (v2 > m) m = v2;
            }
            // token id < 2^24: exact in fp32
            out[row] = (float)(~(unsigned int)(m & 0xFFFFFFFFull));
            g_count[row] = 0;   // self-clean for the next graph replay
        }
    }
}

extern "C" void kernel_launch(void* const* d_in, const int* in_sizes, int n_in,
                              void* d_out, int out_size)
{
    // Identify inputs by SIZE, not order: temperatures -> unique smallest [B];
    // logits/exp_noise -> the big pair (disambiguated on-device by sign).
    int smallIdx = 0;
    for (int i = 1; i < n_in; i++)
        if (in_sizes[i] < in_sizes[smallIdx]) smallIdx = i;

    int bigIdx0 = -1, bigIdx1 = -1;
    for (int i = 0; i < n_in; i++) {
        if (i == smallIdx) continue;
        if (bigIdx0 < 0) bigIdx0 = i; else bigIdx1 = i;
    }

    const float* temps = (const float*)d_in[smallIdx];
    const float* big0  = (const float*)d_in[bigIdx0];
    const float* big1  = (const float*)d_in[bigIdx1];
    float* out = (float*)d_out;                 // __output__ is float32

    const int B = in_sizes[smallIdx];           // 256
    const int V = in_sizes[bigIdx0] / B;        // 128000

    // Grid covers the max chunk count (2 per row); surplus CTAs exit early.
    draft_sampler_kernel<<<2 * B, BLOCK>>>(big0, big1, temps, out, B, V);
}